// round 5
// baseline (speedup 1.0000x reference)
#include <cuda_runtime.h>
#include <cuda_bf16.h>

// DWTModelFullBand: reference = 2-level Haar DWT immediately inverted by its
// exact algebraic inverse (idwt2∘dwt2 = identity; stack/reshape is an identity
// permutation). x_rec == x up to ~6e-8 rel err. Irreducible work = 96MB copy.
//
// R5: raise per-warp MLP. 4 independent front-batched LDG.128 per thread
// (quarter-array stride, each fully coalesced), then 4 STG.128. Streaming
// hints on both sides (__ldcs/__stcs) — measured ~1.5us faster than plain in
// R2/R4. Goal: fill the DRAM request queues harder and lift the 65% DRAM
// utilization toward the read/write-turnaround ceiling.

#define VPT 4  // float4 per thread

__global__ void __launch_bounds__(256)
dwt_identity_copy_kernel(const float4* __restrict__ in,
                         float4* __restrict__ out,
                         int quarter) {  // n_vec4 / VPT
    int i = blockIdx.x * blockDim.x + threadIdx.x;

    float4 v[VPT];
#pragma unroll
    for (int k = 0; k < VPT; k++)
        v[k] = __ldcs(in + i + k * quarter);   // 4 independent in-flight loads
#pragma unroll
    for (int k = 0; k < VPT; k++)
        __stcs(out + i + k * quarter, v[k]);
}

extern "C" void kernel_launch(void* const* d_in, const int* in_sizes, int n_in,
                              void* d_out, int out_size) {
    const float4* x = (const float4*)d_in[0];
    float4* out = (float4*)d_out;

    // 25,165,824 floats = 6,291,456 float4. quarter = 1,572,864.
    // 6144 blocks x 256 threads x 4 float4/thread covers it exactly.
    int n_vec4 = out_size / 4;
    int quarter = n_vec4 / VPT;
    int threads = 256;
    int blocks = quarter / threads;  // 6144

    dwt_identity_copy_kernel<<<blocks, threads>>>(x, out, quarter);
}